// round 7
// baseline (speedup 1.0000x reference)
#include <cuda_runtime.h>
#include <math.h>

// Problem: tensor [8192, 256] fp32.
// out = (adj @ X) where adj = rownorm(cosine_sim(X)).
// Factored: M = X_hat^T X (256x256, SYMMETRIC), s = sum_j x_hat_j (256),
//           out[i] = (x_i @ M) / (x_i . s)   (inv-norm cancels).
// Denominator via compensated fp32 (Dot2). GEMM inner loops use packed
// fma.rn.f32x2 with ZERO repack movs: A-panel stored duplicated in smem,
// B pairs loaded directly as aligned 64-bit words.

#define NROWS 8192
#define DDIM  256
#define GCHUNKS 64          // gram K-chunks: 128 rows each
#define SCHUNKS 256         // norm/s blocks: 32 rows each
#define NTILES  10          // upper-triangle 64x64 tiles of the 4x4 tile grid

typedef unsigned long long ull;

__device__ float  g_invn[NROWS];
__device__ float2 g_spart[SCHUNKS][DDIM];
__device__ float2 g_s2[DDIM];
__device__ float  g_rinv[NROWS];
__device__ float  g_Mpart[GCHUNKS][NTILES][64 * 64];
__device__ float  g_M[DDIM * DDIM];

__device__ const int c_TI[NTILES] = {0,0,0,0,1,1,1,2,2,3};
__device__ const int c_TJ[NTILES] = {0,1,2,3,1,2,3,2,3,3};

// ---- error-free fp32 transforms ------------------------------------------
__device__ __forceinline__ void twoSum(float a, float b, float& s, float& e) {
    s = a + b;
    float bb = s - a;
    e = (a - (s - bb)) + (b - bb);
}
__device__ __forceinline__ void twoProd(float a, float b, float& p, float& e) {
    p = a * b;
    e = fmaf(a, b, -p);
}

// ---- packed f32x2 FMA (sm_100+): d += a*b elementwise on 2 lanes ----------
__device__ __forceinline__ void fma2(ull& d, ull a, ull b) {
    asm("fma.rn.f32x2 %0, %1, %2, %3;" : "=l"(d) : "l"(a), "l"(b), "l"(d));
}
__device__ __forceinline__ float2 unpack2(ull v) {
    float lo, hi;
    asm("mov.b64 {%0, %1}, %2;" : "=f"(lo), "=f"(hi) : "l"(v));
    return make_float2(lo, hi);
}

// ---------------------------------------------------------------------------
// Kernel 1: per-row inverse norms + compensated fp32 partial column sums of
// X_hat. 256 blocks x 256 threads; block b handles rows [b*32, +32).
// ---------------------------------------------------------------------------
__global__ void __launch_bounds__(256) k_norm_s(const float* __restrict__ X) {
    __shared__ float invn_sh[32];
    const int row0 = blockIdx.x * 32;
    const int wid  = threadIdx.x >> 5;
    const int lane = threadIdx.x & 31;

    for (int r = wid; r < 32; r += 8) {
        const float4* p = reinterpret_cast<const float4*>(X + (size_t)(row0 + r) * DDIM);
        float ss = 0.f;
        #pragma unroll
        for (int q = 0; q < 2; q++) {
            float4 v = p[lane + q * 32];
            ss += v.x * v.x + v.y * v.y + v.z * v.z + v.w * v.w;
        }
        #pragma unroll
        for (int o = 16; o > 0; o >>= 1) ss += __shfl_xor_sync(0xffffffffu, ss, o);
        if (lane == 0) {
            float inv = 1.0f / fmaxf(sqrtf(ss), 1e-8f);
            invn_sh[r]       = inv;
            g_invn[row0 + r] = inv;
        }
    }
    __syncthreads();

    const int t = threadIdx.x;
    float s = 0.f, c = 0.f;
    #pragma unroll
    for (int r = 0; r < 32; r++) {
        float p, e, t1;
        twoProd(invn_sh[r], X[(size_t)(row0 + r) * DDIM + t], p, e);
        twoSum(s, p, s, t1);
        c += t1 + e;
    }
    g_spart[blockIdx.x][t] = make_float2(s, c);
}

// ---------------------------------------------------------------------------
// Kernel 2: partial Gram, upper-triangle 64x64 tiles (M symmetric).
// grid = (64 k-chunks x 128 rows, 10 tiles), 256 threads, 4x4 per thread.
// SA stored DUPLICATED (a0,a0,a1,a1,...): f32x2 operands load with no movs.
// ---------------------------------------------------------------------------
__global__ void __launch_bounds__(256) k_gram(const float* __restrict__ X) {
    __shared__ float SA[8][128];   // duplicated: 64 a-values -> 128 floats
    __shared__ float SB[8][64];

    const int c  = blockIdx.x;
    const int t  = blockIdx.y;
    const int ti = c_TI[t];
    const int tj = c_TJ[t];
    const int tx = threadIdx.x & 15;
    const int ty = (threadIdx.x >> 4) & 15;
    const int side = threadIdx.x >> 7;          // 0: SA loader, 1: SB loader
    const int li   = (threadIdx.x >> 4) & 7;    // stage row 0..7
    const int lf   = threadIdx.x & 15;          // float4 slot 0..15
    const int rowbase = c * 128;
    const int colbase = (side == 0 ? ti : tj) * 64;

    ull T2[4][2];
    #pragma unroll
    for (int i = 0; i < 4; i++) { T2[i][0] = 0ull; T2[i][1] = 0ull; }

    for (int kk = 0; kk < 128; kk += 8) {
        const int gr = rowbase + kk + li;
        float4 v = *reinterpret_cast<const float4*>(X + (size_t)gr * DDIM + colbase + lf * 4);
        const float sc = (side == 0) ? g_invn[gr] : 1.0f;
        __syncthreads();   // previous iteration's smem reads done
        if (side == 0) {
            const float ax = v.x * sc, ay = v.y * sc, az = v.z * sc, aw = v.w * sc;
            *reinterpret_cast<float4*>(&SA[li][lf * 8])     = make_float4(ax, ax, ay, ay);
            *reinterpret_cast<float4*>(&SA[li][lf * 8 + 4]) = make_float4(az, az, aw, aw);
        } else {
            *reinterpret_cast<float4*>(&SB[li][lf * 4]) = v;
        }
        __syncthreads();
        #pragma unroll
        for (int r = 0; r < 8; r++) {
            const ulonglong2 a01 = *reinterpret_cast<const ulonglong2*>(&SA[r][ty * 8]);
            const ulonglong2 a23 = *reinterpret_cast<const ulonglong2*>(&SA[r][ty * 8 + 4]);
            const ulonglong2 bp  = *reinterpret_cast<const ulonglong2*>(&SB[r][tx * 4]);
            fma2(T2[0][0], a01.x, bp.x); fma2(T2[0][1], a01.x, bp.y);
            fma2(T2[1][0], a01.y, bp.x); fma2(T2[1][1], a01.y, bp.y);
            fma2(T2[2][0], a23.x, bp.x); fma2(T2[2][1], a23.x, bp.y);
            fma2(T2[3][0], a23.y, bp.x); fma2(T2[3][1], a23.y, bp.y);
        }
    }

    float* out = &g_Mpart[c][t][0];
    #pragma unroll
    for (int i = 0; i < 4; i++) {
        float2 lo = unpack2(T2[i][0]);
        float2 hi = unpack2(T2[i][1]);
        *reinterpret_cast<float4*>(&out[(ty * 4 + i) * 64 + tx * 4]) =
            make_float4(lo.x, lo.y, hi.x, hi.y);
    }
}

// ---------------------------------------------------------------------------
// Kernel 3: compensated fp32 reduce of Mpart (with symmetric mirror) and the
// s-partial pairs. 160 blocks x 256 threads cover 10*4096 upper-tile elems.
// ---------------------------------------------------------------------------
__global__ void __launch_bounds__(256) k_reduce() {
    const int idx = blockIdx.x * 256 + threadIdx.x;   // 0..40959
    const int t = idx >> 12;
    const int e = idx & 4095;
    float s = 0.f, comp = 0.f;
    #pragma unroll
    for (int c = 0; c < GCHUNKS; c++) {
        float t1;
        twoSum(s, g_Mpart[c][t][e], s, t1);
        comp += t1;
    }
    const float v = s + comp;
    const int k = c_TI[t] * 64 + (e >> 6);
    const int l = c_TJ[t] * 64 + (e & 63);
    if (k < l) {
        g_M[k * DDIM + l] = v;
        g_M[l * DDIM + k] = v;
    } else if (k == l) {
        g_M[k * DDIM + l] = v;
    }

    if (blockIdx.x == 0) {
        float sa = 0.f, ca = 0.f;
        #pragma unroll 8
        for (int b = 0; b < SCHUNKS; b++) {
            float2 p = g_spart[b][threadIdx.x];
            float t1;
            twoSum(sa, p.x, sa, t1);
            ca += t1 + p.y;
        }
        g_s2[threadIdx.x] = make_float2(sa, ca);
    }
}

// ---------------------------------------------------------------------------
// Kernel 4: rinv[i] = 1 / (x_i . s) via fp32 Dot2, one row per warp,
// float4 global loads.
// ---------------------------------------------------------------------------
__global__ void __launch_bounds__(256) k_rinv(const float* __restrict__ X) {
    __shared__ float2 s_sh[DDIM];
    s_sh[threadIdx.x] = g_s2[threadIdx.x];
    __syncthreads();
    const int wid  = threadIdx.x >> 5;
    const int lane = threadIdx.x & 31;
    const int row  = blockIdx.x * 8 + wid;

    const float4* xp4 = reinterpret_cast<const float4*>(X + (size_t)row * DDIM);
    float s = 0.f, c = 0.f;
    #pragma unroll
    for (int q = 0; q < 2; q++) {
        const int f = lane + q * 32;
        const float4 xv = xp4[f];
        const float xs[4] = {xv.x, xv.y, xv.z, xv.w};
        #pragma unroll
        for (int m = 0; m < 4; m++) {
            const float2 sv = s_sh[f * 4 + m];
            float p, e, t1;
            twoProd(xs[m], sv.x, p, e);
            e = fmaf(xs[m], sv.y, e);
            twoSum(s, p, s, t1);
            c += t1 + e;
        }
    }
    #pragma unroll
    for (int o = 16; o > 0; o >>= 1) {
        float s2 = __shfl_xor_sync(0xffffffffu, s, o);
        float c2 = __shfl_xor_sync(0xffffffffu, c, o);
        float t1;
        twoSum(s, s2, s, t1);
        c += c2 + t1;
    }
    if (lane == 0) {
        double den = (double)s + (double)c;
        g_rinv[row] = (float)(1.0 / den);
    }
}

// ---------------------------------------------------------------------------
// Kernel 5: OUT = (X @ M) * rinv rowwise.
// grid = (128 row tiles, 4 col tiles) = 512 blocks, 256 threads, 4x4/thread.
// SA holds transposed X rows DUPLICATED along the row axis: SA[k][2*row].
// ---------------------------------------------------------------------------
__global__ void __launch_bounds__(256) k_out(const float* __restrict__ X,
                                             float* __restrict__ OUT) {
    __shared__ float SA[8][128];   // [k][2*row], duplicated
    __shared__ float SB[8][64];

    const int row0 = blockIdx.x * 64;
    const int c0   = blockIdx.y * 64;
    const int tx   = threadIdx.x & 15;
    const int ty   = (threadIdx.x >> 4) & 15;

    const int ar = threadIdx.x >> 1;          // SA loader: row 0..63 (tid<128)
    const int ah = threadIdx.x & 1;           // SA loader: k-half
    const int bi = (threadIdx.x >> 4) & 7;    // SB loader: stage row
    const int bf = threadIdx.x & 15;          // SB loader: float4 slot

    ull T2[4][2];
    #pragma unroll
    for (int i = 0; i < 4; i++) { T2[i][0] = 0ull; T2[i][1] = 0ull; }

    for (int k0 = 0; k0 < DDIM; k0 += 8) {
        float4 v;
        if (threadIdx.x < 128)
            v = *reinterpret_cast<const float4*>(X + (size_t)(row0 + ar) * DDIM + k0 + ah * 4);
        else
            v = *reinterpret_cast<const float4*>(&g_M[(k0 + bi) * DDIM + c0 + bf * 4]);
        __syncthreads();
        if (threadIdx.x < 128) {
            *reinterpret_cast<float2*>(&SA[ah * 4 + 0][ar * 2]) = make_float2(v.x, v.x);
            *reinterpret_cast<float2*>(&SA[ah * 4 + 1][ar * 2]) = make_float2(v.y, v.y);
            *reinterpret_cast<float2*>(&SA[ah * 4 + 2][ar * 2]) = make_float2(v.z, v.z);
            *reinterpret_cast<float2*>(&SA[ah * 4 + 3][ar * 2]) = make_float2(v.w, v.w);
        } else {
            *reinterpret_cast<float4*>(&SB[bi][bf * 4]) = v;
        }
        __syncthreads();
        #pragma unroll
        for (int r = 0; r < 8; r++) {
            const ulonglong2 a01 = *reinterpret_cast<const ulonglong2*>(&SA[r][ty * 8]);
            const ulonglong2 a23 = *reinterpret_cast<const ulonglong2*>(&SA[r][ty * 8 + 4]);
            const ulonglong2 bp  = *reinterpret_cast<const ulonglong2*>(&SB[r][tx * 4]);
            fma2(T2[0][0], a01.x, bp.x); fma2(T2[0][1], a01.x, bp.y);
            fma2(T2[1][0], a01.y, bp.x); fma2(T2[1][1], a01.y, bp.y);
            fma2(T2[2][0], a23.x, bp.x); fma2(T2[2][1], a23.x, bp.y);
            fma2(T2[3][0], a23.y, bp.x); fma2(T2[3][1], a23.y, bp.y);
        }
    }

    #pragma unroll
    for (int i = 0; i < 4; i++) {
        const int m = row0 + ty * 4 + i;
        const float rv = g_rinv[m];
        float2 lo = unpack2(T2[i][0]);
        float2 hi = unpack2(T2[i][1]);
        *reinterpret_cast<float4*>(&OUT[(size_t)m * DDIM + c0 + tx * 4]) =
            make_float4(lo.x * rv, lo.y * rv, hi.x * rv, hi.y * rv);
    }
}

extern "C" void kernel_launch(void* const* d_in, const int* in_sizes, int n_in,
                              void* d_out, int out_size) {
    (void)in_sizes; (void)n_in; (void)out_size;
    const float* X = (const float*)d_in[0];
    float* OUT     = (float*)d_out;

    k_norm_s<<<SCHUNKS, 256>>>(X);
    k_gram<<<dim3(GCHUNKS, NTILES), 256>>>(X);
    k_reduce<<<160, 256>>>();
    k_rinv<<<1024, 256>>>(X);
    k_out<<<dim3(128, 4), 256>>>(X, OUT);
}

// round 8
// speedup vs baseline: 1.1547x; 1.1547x over previous
#include <cuda_runtime.h>
#include <math.h>

// Problem: tensor [8192, 256] fp32.
// out = (adj @ X) where adj = rownorm(cosine_sim(X)).
// Factored: M = X_hat^T X (256x256, SYMMETRIC), s = sum_j x_hat_j (256),
//           out[i] = (x_i @ M) / (x_i . s)   (inv-norm cancels).
// Denominator needs ~fp64 accuracy (row_sum cancellation, min |row_sum|~0.01);
// B300 vector FP64 is de-rated -> error-free fp32 transforms (Dot2).
// GEMM mainloops: scalar FFMA 4x4 register tiles (FFMA2 measured: no gain).

#define NROWS 8192
#define DDIM  256
#define GCHUNKS 64          // gram K-chunks: 128 rows each
#define SCHUNKS 256         // norm/s blocks: 32 rows each
#define NTILES  10          // upper-triangle 64x64 tiles of the 4x4 tile grid

__device__ float  g_invn[NROWS];
__device__ float2 g_spart[SCHUNKS][DDIM];   // compensated fp32 pairs (hi, lo)
__device__ float2 g_s2[DDIM];
__device__ float  g_rinv[NROWS];
__device__ float  g_Mpart[GCHUNKS][NTILES][64 * 64];
__device__ float  g_M[DDIM * DDIM];

__device__ const int c_TI[NTILES] = {0,0,0,0,1,1,1,2,2,3};
__device__ const int c_TJ[NTILES] = {0,1,2,3,1,2,3,2,3,3};

// ---- error-free fp32 transforms ------------------------------------------
__device__ __forceinline__ void twoSum(float a, float b, float& s, float& e) {
    s = a + b;
    float bb = s - a;
    e = (a - (s - bb)) + (b - bb);
}
__device__ __forceinline__ void twoProd(float a, float b, float& p, float& e) {
    p = a * b;
    e = fmaf(a, b, -p);
}

// ---------------------------------------------------------------------------
// Kernel 1: per-row inverse norms + compensated fp32 partial column sums of
// X_hat. 256 blocks x 256 threads; block b handles rows [b*32, +32).
// ---------------------------------------------------------------------------
__global__ void __launch_bounds__(256) k_norm_s(const float* __restrict__ X) {
    __shared__ float invn_sh[32];
    const int row0 = blockIdx.x * 32;
    const int wid  = threadIdx.x >> 5;
    const int lane = threadIdx.x & 31;

    // 8 warps x 4 rows: warp-level sum of squares per row.
    for (int r = wid; r < 32; r += 8) {
        const float4* p = reinterpret_cast<const float4*>(X + (size_t)(row0 + r) * DDIM);
        float ss = 0.f;
        #pragma unroll
        for (int q = 0; q < 2; q++) {
            float4 v = p[lane + q * 32];
            ss += v.x * v.x + v.y * v.y + v.z * v.z + v.w * v.w;
        }
        #pragma unroll
        for (int o = 16; o > 0; o >>= 1) ss += __shfl_xor_sync(0xffffffffu, ss, o);
        if (lane == 0) {
            float inv = 1.0f / fmaxf(sqrtf(ss), 1e-8f);
            invn_sh[r]       = inv;
            g_invn[row0 + r] = inv;
        }
    }
    __syncthreads();

    // Dot2 column sum over 32 rows: thread t owns column t (coalesced).
    const int t = threadIdx.x;
    float s = 0.f, c = 0.f;
    #pragma unroll
    for (int r = 0; r < 32; r++) {
        float p, e, t1;
        twoProd(invn_sh[r], X[(size_t)(row0 + r) * DDIM + t], p, e);
        twoSum(s, p, s, t1);
        c += t1 + e;
    }
    g_spart[blockIdx.x][t] = make_float2(s, c);
}

// ---------------------------------------------------------------------------
// Kernel 2: partial Gram, upper-triangle tiles only (M is symmetric).
// grid = (64 k-chunks, 10 tiles), 256 threads, 4x4 register tile per thread.
// ---------------------------------------------------------------------------
__global__ void __launch_bounds__(256) k_gram(const float* __restrict__ X) {
    __shared__ float SA[8][64];
    __shared__ float SB[8][64];

    const int c  = blockIdx.x;
    const int t  = blockIdx.y;
    const int ti = c_TI[t];
    const int tj = c_TJ[t];
    const int tx = threadIdx.x & 15;
    const int ty = (threadIdx.x >> 4) & 15;
    const int side = threadIdx.x >> 7;          // warps 0-3 load SA, 4-7 load SB
    const int li   = (threadIdx.x >> 4) & 7;    // stage row 0..7
    const int lf   = threadIdx.x & 15;          // float4 slot 0..15
    const int rowbase = c * 128;
    const int colbase = (side == 0 ? ti : tj) * 64;

    float T[4][4];
    #pragma unroll
    for (int i = 0; i < 4; i++)
        #pragma unroll
        for (int j = 0; j < 4; j++) T[i][j] = 0.f;

    for (int kk = 0; kk < 128; kk += 8) {
        const int gr = rowbase + kk + li;
        float4 v = *reinterpret_cast<const float4*>(X + (size_t)gr * DDIM + colbase + lf * 4);
        float scale = (side == 0) ? g_invn[gr] : 1.0f;
        __syncthreads();   // previous iteration's smem reads done
        if (side == 0)
            *reinterpret_cast<float4*>(&SA[li][lf * 4]) =
                make_float4(v.x * scale, v.y * scale, v.z * scale, v.w * scale);
        else
            *reinterpret_cast<float4*>(&SB[li][lf * 4]) = v;
        __syncthreads();
        #pragma unroll
        for (int r = 0; r < 8; r++) {
            float4 a = *reinterpret_cast<const float4*>(&SA[r][ty * 4]);
            float4 b = *reinterpret_cast<const float4*>(&SB[r][tx * 4]);
            const float aa[4] = {a.x, a.y, a.z, a.w};
            const float bb[4] = {b.x, b.y, b.z, b.w};
            #pragma unroll
            for (int i = 0; i < 4; i++)
                #pragma unroll
                for (int j = 0; j < 4; j++) T[i][j] += aa[i] * bb[j];
        }
    }

    float* out = &g_Mpart[c][t][0];
    #pragma unroll
    for (int i = 0; i < 4; i++)
        *reinterpret_cast<float4*>(&out[(ty * 4 + i) * 64 + tx * 4]) =
            make_float4(T[i][0], T[i][1], T[i][2], T[i][3]);
}

// ---------------------------------------------------------------------------
// Kernel 3: compensated fp32 reduce of Mpart (with symmetric mirror) and the
// s-partial pairs. 160 blocks x 256 threads cover 10*4096 upper-tile elems.
// ---------------------------------------------------------------------------
__global__ void __launch_bounds__(256) k_reduce() {
    const int idx = blockIdx.x * 256 + threadIdx.x;   // 0..40959
    const int t = idx >> 12;
    const int e = idx & 4095;
    float s = 0.f, comp = 0.f;
    #pragma unroll
    for (int c = 0; c < GCHUNKS; c++) {
        float t1;
        twoSum(s, g_Mpart[c][t][e], s, t1);
        comp += t1;
    }
    const float v = s + comp;
    const int k = c_TI[t] * 64 + (e >> 6);
    const int l = c_TJ[t] * 64 + (e & 63);
    if (k < l) {
        g_M[k * DDIM + l] = v;
        g_M[l * DDIM + k] = v;
    } else if (k == l) {
        g_M[k * DDIM + l] = v;
    } // k > l only inside diagonal tiles: mirror writes it

    if (blockIdx.x == 0) {
        float sa = 0.f, ca = 0.f;
        #pragma unroll 8
        for (int b = 0; b < SCHUNKS; b++) {
            float2 p = g_spart[b][threadIdx.x];
            float t1;
            twoSum(sa, p.x, sa, t1);
            ca += t1 + p.y;
        }
        g_s2[threadIdx.x] = make_float2(sa, ca);
    }
}

// ---------------------------------------------------------------------------
// Kernel 4: rinv[i] = 1 / (x_i . s) via fp32 Dot2, TWO ROWS PER WARP.
// 512 blocks x 256 threads: warp w of block b owns rows (b*16 + w*2) + {0,1}.
// 4 LDG.128 in flight per lane, two independent Dot2 chains for FMA ILP.
// ---------------------------------------------------------------------------
__global__ void __launch_bounds__(256) k_rinv(const float* __restrict__ X) {
    __shared__ float2 s_sh[DDIM];
    s_sh[threadIdx.x] = g_s2[threadIdx.x];
    __syncthreads();
    const int wid  = threadIdx.x >> 5;
    const int lane = threadIdx.x & 31;
    const int row  = blockIdx.x * 16 + wid * 2;

    const float4* xp0 = reinterpret_cast<const float4*>(X + (size_t)row * DDIM);
    const float4* xp1 = reinterpret_cast<const float4*>(X + (size_t)(row + 1) * DDIM);

    // issue all 4 loads up front (MLP=4 per lane)
    const float4 v00 = xp0[lane];
    const float4 v01 = xp0[lane + 32];
    const float4 v10 = xp1[lane];
    const float4 v11 = xp1[lane + 32];

    float s0 = 0.f, c0 = 0.f, s1 = 0.f, c1 = 0.f;
    #pragma unroll
    for (int q = 0; q < 2; q++) {
        const int f = lane + q * 32;
        const float4 a = (q == 0) ? v00 : v01;
        const float4 b = (q == 0) ? v10 : v11;
        const float xa[4] = {a.x, a.y, a.z, a.w};
        const float xb[4] = {b.x, b.y, b.z, b.w};
        #pragma unroll
        for (int m = 0; m < 4; m++) {
            const float2 sv = s_sh[f * 4 + m];
            float p, e, t1;
            // row 0 chain
            twoProd(xa[m], sv.x, p, e);
            e = fmaf(xa[m], sv.y, e);
            twoSum(s0, p, s0, t1);
            c0 += t1 + e;
            // row 1 chain (independent)
            twoProd(xb[m], sv.x, p, e);
            e = fmaf(xb[m], sv.y, e);
            twoSum(s1, p, s1, t1);
            c1 += t1 + e;
        }
    }
    #pragma unroll
    for (int o = 16; o > 0; o >>= 1) {
        float t1;
        float s0b = __shfl_xor_sync(0xffffffffu, s0, o);
        float c0b = __shfl_xor_sync(0xffffffffu, c0, o);
        twoSum(s0, s0b, s0, t1);
        c0 += c0b + t1;
        float s1b = __shfl_xor_sync(0xffffffffu, s1, o);
        float c1b = __shfl_xor_sync(0xffffffffu, c1, o);
        twoSum(s1, s1b, s1, t1);
        c1 += c1b + t1;
    }
    if (lane == 0) {
        g_rinv[row]     = (float)(1.0 / ((double)s0 + (double)c0));
        g_rinv[row + 1] = (float)(1.0 / ((double)s1 + (double)c1));
    }
}

// ---------------------------------------------------------------------------
// Kernel 5: OUT = (X @ M) * rinv rowwise.
// grid = (128 row tiles, 4 col tiles) = 512 blocks, 256 threads, 4x4/thread.
// ---------------------------------------------------------------------------
__global__ void __launch_bounds__(256) k_out(const float* __restrict__ X,
                                             float* __restrict__ OUT) {
    __shared__ float SA[8][68];
    __shared__ float SB[8][64];

    const int row0 = blockIdx.x * 64;
    const int c0   = blockIdx.y * 64;
    const int tx   = threadIdx.x & 15;
    const int ty   = (threadIdx.x >> 4) & 15;

    const int ar = threadIdx.x >> 1;          // SA loader: row (tid<128)
    const int ah = threadIdx.x & 1;           // SA loader: k-half
    const int bi = (threadIdx.x >> 4) & 7;    // SB loader: stage row
    const int bf = threadIdx.x & 15;          // SB loader: float4 slot

    float T[4][4];
    #pragma unroll
    for (int i = 0; i < 4; i++)
        #pragma unroll
        for (int j = 0; j < 4; j++) T[i][j] = 0.f;

    for (int k0 = 0; k0 < DDIM; k0 += 8) {
        float4 v;
        if (threadIdx.x < 128)
            v = *reinterpret_cast<const float4*>(X + (size_t)(row0 + ar) * DDIM + k0 + ah * 4);
        else
            v = *reinterpret_cast<const float4*>(&g_M[(k0 + bi) * DDIM + c0 + bf * 4]);
        __syncthreads();
        if (threadIdx.x < 128) {
            SA[ah * 4 + 0][ar] = v.x;
            SA[ah * 4 + 1][ar] = v.y;
            SA[ah * 4 + 2][ar] = v.z;
            SA[ah * 4 + 3][ar] = v.w;
        } else {
            *reinterpret_cast<float4*>(&SB[bi][bf * 4]) = v;
        }
        __syncthreads();
        #pragma unroll
        for (int r = 0; r < 8; r++) {
            float4 a = *reinterpret_cast<const float4*>(&SA[r][ty * 4]);
            float4 b = *reinterpret_cast<const float4*>(&SB[r][tx * 4]);
            const float aa[4] = {a.x, a.y, a.z, a.w};
            const float bb[4] = {b.x, b.y, b.z, b.w};
            #pragma unroll
            for (int i = 0; i < 4; i++)
                #pragma unroll
                for (int j = 0; j < 4; j++) T[i][j] += aa[i] * bb[j];
        }
    }

    #pragma unroll
    for (int i = 0; i < 4; i++) {
        const int m = row0 + ty * 4 + i;
        const float rv = g_rinv[m];
        *reinterpret_cast<float4*>(&OUT[(size_t)m * DDIM + c0 + tx * 4]) =
            make_float4(T[i][0] * rv, T[i][1] * rv, T[i][2] * rv, T[i][3] * rv);
    }
}

extern "C" void kernel_launch(void* const* d_in, const int* in_sizes, int n_in,
                              void* d_out, int out_size) {
    (void)in_sizes; (void)n_in; (void)out_size;
    const float* X = (const float*)d_in[0];
    float* OUT     = (float*)d_out;

    k_norm_s<<<SCHUNKS, 256>>>(X);
    k_gram<<<dim3(GCHUNKS, NTILES), 256>>>(X);
    k_reduce<<<160, 256>>>();
    k_rinv<<<512, 256>>>(X);
    k_out<<<dim3(128, 4), 256>>>(X, OUT);
}